// round 15
// baseline (speedup 1.0000x reference)
#include <cuda_runtime.h>
#include <cuda_bf16.h>
#include <cuda_fp16.h>
#include <cstdint>

// ---------------------------------------------------------------------------
// Problem constants
// ---------------------------------------------------------------------------
constexpr int T   = 4096;
constexpr int H   = 1024;
constexpr int F   = 2048;
constexpr int E   = 8;
constexpr int CAP = 640;

constexpr int KA1 = H;       // 1024  GEMM1 K
constexpr int KA2 = F;       // 2048  GEMM2 K
constexpr int NB1 = 2 * F;   // 4096  interleaved gate/up rows
constexpr int NB2 = H;       // 1024

constexpr int MT    = CAP / 128;                 // 5 m-tiles
constexpr int N_G1  = E * MT * (NB1 / 128);      // 1280 GEMM1 items
constexpr int N_G2  = E * MT * (NB2 / 128) * 2;  // 640  GEMM2 items (split-K 2)
constexpr int N_CMB = (T * (H / 8)) / 256;       // 2048 combine items
constexpr int N_ALL = N_G1 + N_G2 + N_CMB;       // 3968

// ---------------------------------------------------------------------------
// Scratch
// ---------------------------------------------------------------------------
__device__ float d_tokens_ln[(size_t)T * H];
__device__ int   d_sel[E * CAP];
__device__ int   d_valid[E * CAP];
__device__ int   d_idx[T * 2];
__device__ float d_wts[T * 2];
__device__ int   d_ready[E * MT];                 // GEMM1 completion counters
__device__ int   d_g2done;                        // GEMM2 completion counter
__device__ __align__(16) __half d_xin_fp[(size_t)E * CAP * KA1];
__device__ __align__(16) __half d_wgu_fp[(size_t)E * NB1 * KA1];
__device__ __align__(16) __half d_wd_fp [(size_t)E * NB2 * KA2];
__device__ __align__(16) __half d_act_fp[(size_t)E * CAP * KA2];
__device__ __align__(16) __half d_eout_fp[(size_t)2 * E * CAP * H];  // fp16 split-K partials

// ---------------------------------------------------------------------------
// PTX helpers
// ---------------------------------------------------------------------------
__device__ __forceinline__ uint32_t smem_u32(const void* p) {
    uint32_t a;
    asm("{ .reg .u64 t; cvta.to.shared.u64 t, %1; cvt.u32.u64 %0, t; }" : "=r"(a) : "l"(p));
    return a;
}
#define CP_ASYNC16(dst, src) \
    asm volatile("cp.async.cg.shared.global [%0], [%1], 16;" :: "r"(dst), "l"(src))
#define CP_COMMIT() asm volatile("cp.async.commit_group;" ::: "memory")
#define CP_WAIT2()  asm volatile("cp.async.wait_group 2;" ::: "memory")

__device__ __forceinline__ void ldmx4(uint32_t& r0, uint32_t& r1, uint32_t& r2,
                                      uint32_t& r3, uint32_t a) {
    asm volatile("ldmatrix.sync.aligned.m8n8.x4.shared.b16 {%0,%1,%2,%3}, [%4];"
                 : "=r"(r0), "=r"(r1), "=r"(r2), "=r"(r3) : "r"(a));
}
__device__ __forceinline__ void mma_f16(float* c, uint32_t a0, uint32_t a1,
                                        uint32_t a2, uint32_t a3,
                                        uint32_t b0, uint32_t b1) {
    asm volatile(
        "mma.sync.aligned.m16n8k16.row.col.f32.f16.f16.f32 "
        "{%0,%1,%2,%3}, {%4,%5,%6,%7}, {%8,%9}, {%0,%1,%2,%3};"
        : "+f"(c[0]), "+f"(c[1]), "+f"(c[2]), "+f"(c[3])
        : "r"(a0), "r"(a1), "r"(a2), "r"(a3), "r"(b0), "r"(b1));
}
__device__ __forceinline__ void spin_until(const int* p, int target) {
    int v;
    do {
        asm volatile("ld.acquire.gpu.global.b32 %0, [%1];"
                     : "=r"(v) : "l"(p) : "memory");
        if (v < target) __nanosleep(64);
    } while (v < target);
}

// ---------------------------------------------------------------------------
// Kernel A: LayerNorm + router + top-2 (one block / token), shuffle reductions
// ---------------------------------------------------------------------------
__global__ void __launch_bounds__(256) ln_router_kernel(
    const float* __restrict__ x, const float* __restrict__ rw,
    const float* __restrict__ gamma, const float* __restrict__ beta)
{
    int t   = blockIdx.x;
    int tid = threadIdx.x;
    int warp = tid >> 5, lane = tid & 31;
    const float4 v = ((const float4*)(x + (size_t)t * H))[tid];

    __shared__ float wsum[8];
    __shared__ float bcast;

    float s = v.x + v.y + v.z + v.w;
    #pragma unroll
    for (int o = 16; o > 0; o >>= 1) s += __shfl_down_sync(0xffffffffu, s, o);
    if (lane == 0) wsum[warp] = s;
    __syncthreads();
    if (warp == 0) {
        float sv = (lane < 8) ? wsum[lane] : 0.0f;
        #pragma unroll
        for (int o = 4; o > 0; o >>= 1) sv += __shfl_down_sync(0xffffffffu, sv, o);
        if (lane == 0) bcast = sv;
    }
    __syncthreads();
    float mu = bcast * (1.0f / H);
    __syncthreads();

    float dx0 = v.x - mu, dx1 = v.y - mu, dx2 = v.z - mu, dx3 = v.w - mu;
    s = dx0 * dx0 + dx1 * dx1 + dx2 * dx2 + dx3 * dx3;
    #pragma unroll
    for (int o = 16; o > 0; o >>= 1) s += __shfl_down_sync(0xffffffffu, s, o);
    if (lane == 0) wsum[warp] = s;
    __syncthreads();
    if (warp == 0) {
        float sv = (lane < 8) ? wsum[lane] : 0.0f;
        #pragma unroll
        for (int o = 4; o > 0; o >>= 1) sv += __shfl_down_sync(0xffffffffu, sv, o);
        if (lane == 0) bcast = sv;
    }
    __syncthreads();
    float rstd = rsqrtf(bcast * (1.0f / H) + 1e-5f);

    float4 g4 = ((const float4*)gamma)[tid];
    float4 b4 = ((const float4*)beta)[tid];
    float tl[4];
    tl[0] = dx0 * rstd * g4.x + b4.x;
    tl[1] = dx1 * rstd * g4.y + b4.y;
    tl[2] = dx2 * rstd * g4.z + b4.z;
    tl[3] = dx3 * rstd * g4.w + b4.w;
    ((float4*)(d_tokens_ln + (size_t)t * H))[tid] = make_float4(tl[0], tl[1], tl[2], tl[3]);

    int h0 = tid * 4;
    float acc[E];
    #pragma unroll
    for (int e = 0; e < E; e++) acc[e] = 0.0f;
    #pragma unroll
    for (int j = 0; j < 4; j++) {
        const float* rwr = rw + (size_t)(h0 + j) * E;
        #pragma unroll
        for (int e = 0; e < E; e++) acc[e] += tl[j] * rwr[e];
    }
    #pragma unroll
    for (int off = 16; off > 0; off >>= 1)
        #pragma unroll
        for (int e = 0; e < E; e++)
            acc[e] += __shfl_down_sync(0xffffffffu, acc[e], off);

    __shared__ float wlog[8][E];
    if (lane == 0)
        #pragma unroll
        for (int e = 0; e < E; e++) wlog[warp][e] = acc[e];
    __syncthreads();

    if (tid == 0) {
        float lg[E];
        #pragma unroll
        for (int e = 0; e < E; e++) {
            float sv = 0.0f;
            #pragma unroll
            for (int w = 0; w < 8; w++) sv += wlog[w][e];
            lg[e] = sv;
        }
        float mx = lg[0];
        #pragma unroll
        for (int e = 1; e < E; e++) mx = fmaxf(mx, lg[e]);
        float p[E];
        #pragma unroll
        for (int e = 0; e < E; e++) p[e] = expf(lg[e] - mx);
        int i0 = 0; float b0 = p[0];
        #pragma unroll
        for (int e = 1; e < E; e++) if (p[e] > b0) { b0 = p[e]; i0 = e; }
        int i1 = -1; float b1 = -1.0f;
        #pragma unroll
        for (int e = 0; e < E; e++) if (e != i0 && p[e] > b1) { b1 = p[e]; i1 = e; }
        float inv = 1.0f / (b0 + b1);
        d_idx[2 * t] = i0; d_idx[2 * t + 1] = i1;
        d_wts[2 * t] = b0 * inv; d_wts[2 * t + 1] = b1 * inv;
    }
}

// ---------------------------------------------------------------------------
// Kernel B: capacity assignment (stable), one block / expert
// ---------------------------------------------------------------------------
__global__ void __launch_bounds__(1024) assign_kernel()
{
    int e = blockIdx.x, tid = threadIdx.x;
    int lane = tid & 31, warp = tid >> 5;
    __shared__ int warpCnt[32];
    __shared__ int s_totalSel, s_runSel, s_runUnsel, s_chunkSel;

    int cnt = 0;
    for (int t = tid; t < T; t += 1024)
        cnt += (d_idx[2 * t] == e) | (d_idx[2 * t + 1] == e);
    #pragma unroll
    for (int off = 16; off > 0; off >>= 1) cnt += __shfl_down_sync(0xffffffffu, cnt, off);
    if (lane == 0) warpCnt[warp] = cnt;
    __syncthreads();
    if (tid == 0) {
        int sv = 0;
        for (int w = 0; w < 32; w++) sv += warpCnt[w];
        s_totalSel = sv; s_runSel = 0; s_runUnsel = 0;
    }
    __syncthreads();
    int totalSel = s_totalSel;

    for (int base = 0; base < T; base += 1024) {
        int t = base + tid;
        int m = (d_idx[2 * t] == e) | (d_idx[2 * t + 1] == e);
        unsigned bal = __ballot_sync(0xffffffffu, m);
        int wpre = __popc(bal & ((1u << lane) - 1u));
        if (lane == 0) warpCnt[warp] = __popc(bal);
        __syncthreads();
        if (tid == 0) {
            int sv = 0;
            for (int w = 0; w < 32; w++) { int c = warpCnt[w]; warpCnt[w] = sv; sv += c; }
            s_chunkSel = sv;
        }
        __syncthreads();
        int selPre = warpCnt[warp] + wpre;
        int rs = s_runSel, ru = s_runUnsel;
        int pos = m ? (rs + selPre) : (totalSel + ru + (tid - selPre));
        if (pos < CAP) { d_sel[e * CAP + pos] = t; d_valid[e * CAP + pos] = m; }
        __syncthreads();
        if (tid == 0) { s_runSel = rs + s_chunkSel; s_runUnsel = ru + (1024 - s_chunkSel); }
        __syncthreads();
    }
}

// ---------------------------------------------------------------------------
// Kernel C: gather + fp16 convert; block 0 also resets the ready counters
// ---------------------------------------------------------------------------
__global__ void __launch_bounds__(128) gather_convert_kernel()
{
    int ec = blockIdx.x, tid = threadIdx.x;
    if (ec == 0) {
        if (tid < E * MT) d_ready[tid] = 0;
        if (tid == 0) d_g2done = 0;
    }
    int v = d_valid[ec], s = d_sel[ec];
    float4 a = make_float4(0.f,0.f,0.f,0.f), b = a;
    if (v) {
        const float4* src = (const float4*)(d_tokens_ln + (size_t)s * H);
        a = src[tid * 2]; b = src[tid * 2 + 1];
    }
    float vv[8] = {a.x, a.y, a.z, a.w, b.x, b.y, b.z, b.w};
    alignas(16) __half o[8];
    #pragma unroll
    for (int j = 0; j < 8; j++) o[j] = __float2half(vv[j]);
    ((uint4*)(d_xin_fp + (size_t)ec * KA1 + tid * 8))[0] = *(const uint4*)o;
}

// ---------------------------------------------------------------------------
// Kernel D: gate/up transpose [E][H][F] -> [E][2F][H] fp16 (rows 2f+s)
// ---------------------------------------------------------------------------
__global__ void __launch_bounds__(256) conv_gateup_kernel(
    const float* __restrict__ wg, const float* __restrict__ wu)
{
    int f0 = blockIdx.x * 32, h0 = blockIdx.y * 64, e = blockIdx.z;
    __shared__ float sg[32][65], su[32][65];
    int t = threadIdx.x, fi = t & 31, hr = t >> 5;
    #pragma unroll
    for (int it = 0; it < 8; it++) {
        int hl = hr + it * 8;
        size_t base = ((size_t)e * H + h0 + hl) * F + f0 + fi;
        sg[fi][hl] = wg[base];
        su[fi][hl] = wu[base];
    }
    __syncthreads();
    #pragma unroll
    for (int it = 0; it < 2; it++) {
        int u = t + it * 256;
        int r = u >> 3, unit = u & 7;
        int fl = r >> 1, sfl = r & 1;
        const float (*sm)[65] = sfl ? su : sg;
        alignas(16) __half o[8];
        #pragma unroll
        for (int j = 0; j < 8; j++) o[j] = __float2half(sm[fl][unit * 8 + j]);
        ((uint4*)(d_wgu_fp + ((size_t)e * NB1 + 2 * f0 + r) * KA1
                  + h0 + unit * 8))[0] = *(const uint4*)o;
    }
}

// ---------------------------------------------------------------------------
// Kernel E: down transpose [E][F][H] -> [E][H][F] fp16
// ---------------------------------------------------------------------------
__global__ void __launch_bounds__(256) conv_down_kernel(const float* __restrict__ wd)
{
    int f0 = blockIdx.x * 64, h0 = blockIdx.y * 32, e = blockIdx.z;
    __shared__ float sd[32][65];
    int t = threadIdx.x, hl = t & 31, fr = t >> 5;
    #pragma unroll
    for (int it = 0; it < 8; it++) {
        int fl = fr + it * 8;
        sd[hl][fl] = wd[((size_t)e * F + f0 + fl) * H + h0 + hl];
    }
    __syncthreads();
    {
        int r = t >> 3, unit = t & 7;
        alignas(16) __half o[8];
        #pragma unroll
        for (int j = 0; j < 8; j++) o[j] = __float2half(sd[r][unit * 8 + j]);
        ((uint4*)(d_wd_fp + ((size_t)e * NB2 + h0 + r) * KA2
                  + f0 + unit * 8))[0] = *(const uint4*)o;
    }
}

// ---------------------------------------------------------------------------
// FUSED launch: one kernel, 3968 CTAs, three item types in bid order:
//   [0, 1280)      GEMM1 tiles  -> silu -> d_act_fp, bump ready[e][m0]
//   [1280, 1920)   GEMM2 tiles  (spin on ready[e][m0]==32) -> d_eout_fp,
//                  bump d_g2done
//   [1920, 3968)   combine CTAs (spin on d_g2done==640) -> out
// Bid-order dispatch makes every spin deadlock-free; later phases backfill
// earlier phases' wave drains. Mainloop = proven 128x128/BK32/occ2 pipeline.
// ---------------------------------------------------------------------------
constexpr int STAGE_BYTES = 20480;            // A 128*80 + B 128*80
constexpr int GEMM_SMEM   = 4 * STAGE_BYTES;  // 81920

__global__ void __launch_bounds__(256, 2) fused_gemm_kernel(
    const float* __restrict__ x, float* __restrict__ out)
{
    constexpr int NC = 32;                    // K=1024 for both GEMM item types
    extern __shared__ char smem_raw[];
    uint32_t sb = smem_u32(smem_raw);
    int tid = threadIdx.x, wid = tid >> 5, lane = tid & 31;
    int bid = blockIdx.x;

    // ---------------- combine item ----------------
    if (bid >= N_G1 + N_G2) {
        if (tid == 0) spin_until(&d_g2done, N_G2);
        __syncthreads();
        constexpr int PART = E * CAP * (H / 8);
        int i = (bid - N_G1 - N_G2) * 256 + tid;
        int h8 = i & (H / 8 - 1);
        int t  = i >> 7;
        int slot = min(t, CAP - 1);
        int i0 = d_idx[2 * t], i1 = d_idx[2 * t + 1];
        float w0 = d_wts[2 * t], w1 = d_wts[2 * t + 1];
        const uint4* e4 = (const uint4*)d_eout_fp;
        int idx0 = (i0 * CAP + slot) * (H / 8) + h8;
        int idx1 = (i1 * CAP + slot) * (H / 8) + h8;
        uint4 q0a = e4[idx0], q0b = e4[idx0 + PART];
        uint4 q1a = e4[idx1], q1b = e4[idx1 + PART];
        const __half2* g0a = (const __half2*)&q0a;
        const __half2* g0b = (const __half2*)&q0b;
        const __half2* g1a = (const __half2*)&q1a;
        const __half2* g1b = (const __half2*)&q1b;
        const float4* x4 = (const float4*)x;
        float4* o4 = (float4*)out;
        #pragma unroll
        for (int q = 0; q < 2; q++) {
            float4 a = x4[i * 2 + q];
            float2 p0a = __half22float2(g0a[q * 2]), p0a1 = __half22float2(g0a[q * 2 + 1]);
            float2 p0b = __half22float2(g0b[q * 2]), p0b1 = __half22float2(g0b[q * 2 + 1]);
            float2 p1a = __half22float2(g1a[q * 2]), p1a1 = __half22float2(g1a[q * 2 + 1]);
            float2 p1b = __half22float2(g1b[q * 2]), p1b1 = __half22float2(g1b[q * 2 + 1]);
            float4 o;
            o.x = a.x + w0 * (p0a.x  + p0b.x)  + w1 * (p1a.x  + p1b.x);
            o.y = a.y + w0 * (p0a.y  + p0b.y)  + w1 * (p1a.y  + p1b.y);
            o.z = a.z + w0 * (p0a1.x + p0b1.x) + w1 * (p1a1.x + p1b1.x);
            o.w = a.w + w0 * (p0a1.y + p0b1.y) + w1 * (p1a1.y + p1b1.y);
            o4[i * 2 + q] = o;
        }
        return;
    }

    // ---------------- GEMM items ----------------
    bool g1 = bid < N_G1;
    int e, m0, n0, part = 0;
    const __half *Arow, *Brow;
    size_t ktb;
    if (g1) {
        e = bid / (MT * (NB1 / 128));
        int rem = bid % (MT * (NB1 / 128));
        m0 = (rem % MT) * 128;
        n0 = (rem / MT) * 128;
        Arow = d_xin_fp + ((size_t)e * CAP + m0) * KA1;
        Brow = d_wgu_fp + ((size_t)e * NB1 + n0) * KA1;
        ktb  = KA1 * 2;
    } else {
        int idx = bid - N_G1;
        e = idx / (MT * (NB2 / 128) * 2);
        int rem = idx % (MT * (NB2 / 128) * 2);
        part = rem & 1;
        rem >>= 1;
        m0 = (rem % MT) * 128;
        n0 = (rem / MT) * 128;
        Arow = d_act_fp + ((size_t)e * CAP + m0) * KA2 + part * (KA2 / 2);
        Brow = d_wd_fp  + ((size_t)e * NB2 + n0) * KA2 + part * (KA2 / 2);
        ktb  = KA2 * 2;
        if (tid == 0) spin_until(&d_ready[e * MT + (m0 >> 7)], 32);
        __syncthreads();
    }

    int wm0 = (wid & 3) * 32, wn0 = (wid >> 2) * 64;
    float acc[2][8][4] = {};

    auto loadst = [&](int s, int chunk) {
        uint32_t abase = sb + s * STAGE_BYTES;
        uint32_t bbase = abase + 10240;
        const char* ag = (const char*)Arow + chunk * 64;
        const char* bg = (const char*)Brow + chunk * 64;
        #pragma unroll
        for (int it = 0; it < 2; it++) {
            int u = tid + it * 256; int row = u >> 2, c = u & 3;
            CP_ASYNC16(abase + row * 80 + c * 16, ag + (size_t)row * ktb + c * 16);
        }
        #pragma unroll
        for (int it = 0; it < 2; it++) {
            int u = tid + it * 256; int row = u >> 2, c = u & 3;
            CP_ASYNC16(bbase + row * 80 + c * 16, bg + (size_t)row * ktb + c * 16);
        }
        CP_COMMIT();
    };

    #pragma unroll
    for (int s = 0; s < 3; s++) loadst(s, s);

    for (int i = 0; i < NC; i++) {
        int s = i & 3;
        CP_WAIT2();
        __syncthreads();
        if (i + 3 < NC) loadst((i + 3) & 3, i + 3);
        else            CP_COMMIT();
        uint32_t abase = sb + s * STAGE_BYTES;
        uint32_t bbase = abase + 10240;
        #pragma unroll
        for (int kk = 0; kk < 2; kk++) {
            uint32_t a[2][4];
            #pragma unroll
            for (int ms = 0; ms < 2; ms++) {
                uint32_t ad = abase + (wm0 + ms * 16 + (lane & 15)) * 80
                            + (kk * 2 + (lane >> 4)) * 16;
                ldmx4(a[ms][0], a[ms][1], a[ms][2], a[ms][3], ad);
            }
            #pragma unroll
            for (int np = 0; np < 4; np++) {
                uint32_t b0, b1, b2, b3;
                uint32_t bd = bbase + (wn0 + np * 16 + (lane & 7) + ((lane >> 4) << 3)) * 80
                            + (kk * 2 + ((lane >> 3) & 1)) * 16;
                ldmx4(b0, b1, b2, b3, bd);
                #pragma unroll
                for (int ms = 0; ms < 2; ms++) {
                    mma_f16(acc[ms][np * 2],     a[ms][0], a[ms][1], a[ms][2], a[ms][3], b0, b1);
                    mma_f16(acc[ms][np * 2 + 1], a[ms][0], a[ms][1], a[ms][2], a[ms][3], b2, b3);
                }
            }
        }
    }

    // -------- epilogue --------
    if (g1) {
        __syncthreads();
        __half* sact = (__half*)smem_raw;
        #pragma unroll
        for (int ms = 0; ms < 2; ms++) {
            #pragma unroll
            for (int np = 0; np < 8; np++) {
                int f_l = (wn0 >> 1) + np * 4 + (lane & 3);
                #pragma unroll
                for (int h = 0; h < 2; h++) {
                    int row_l = wm0 + ms * 16 + (lane >> 2) + h * 8;
                    float g  = acc[ms][np][2 * h];
                    float uu = acc[ms][np][2 * h + 1];
                    float av = (g / (1.0f + __expf(-g))) * uu;
                    sact[row_l * 64 + f_l] = __float2half(av);
                }
            }
        }
        __syncthreads();
        int row = tid >> 1, half = tid & 1;
        const uint4* src = (const uint4*)(sact + row * 64) + half * 4;
        uint4* dst = (uint4*)(d_act_fp + ((size_t)e * CAP + m0 + row) * KA2
                              + (n0 >> 1)) + half * 4;
        #pragma unroll
        for (int q = 0; q < 4; q++) dst[q] = src[q];
        __threadfence();
        __syncthreads();
        if (tid == 0) atomicAdd(&d_ready[e * MT + (m0 >> 7)], 1);
    } else {
        __half* outp = d_eout_fp + (size_t)part * E * CAP * H;
        #pragma unroll
        for (int ms = 0; ms < 2; ms++) {
            #pragma unroll
            for (int np = 0; np < 8; np++) {
                int r0 = m0 + wm0 + ms * 16 + (lane >> 2);
                int nc = n0 + wn0 + np * 8 + (lane & 3) * 2;
                #pragma unroll
                for (int h = 0; h < 2; h++) {
                    int row = r0 + h * 8;
                    __half2* p = (__half2*)(outp + ((size_t)e * CAP + row) * H + nc);
                    *p = __floats2half2_rn(acc[ms][np][2 * h], acc[ms][np][2 * h + 1]);
                }
            }
        }
        __threadfence();
        __syncthreads();
        if (tid == 0) atomicAdd(&d_g2done, 1);
    }
}

// ---------------------------------------------------------------------------
// Launch: conv kernels on the 2 proven side streams; single fused launch
// covering GEMM1 + GEMM2 + combine.
// ---------------------------------------------------------------------------
extern "C" void kernel_launch(void* const* d_in, const int* in_sizes, int n_in,
                              void* d_out, int out_size)
{
    const float* x     = (const float*)d_in[0];
    const float* rw    = (const float*)d_in[1];
    const float* wg    = (const float*)d_in[2];
    const float* wu    = (const float*)d_in[3];
    const float* wd    = (const float*)d_in[4];
    const float* gamma = (const float*)d_in[5];
    const float* beta  = (const float*)d_in[6];
    float*       out   = (float*)d_out;

    static cudaStream_t s1 = nullptr, s2 = nullptr;
    static cudaEvent_t  ev0 = nullptr, ev1 = nullptr, ev2 = nullptr;
    if (s1 == nullptr) {       // first call is uncaptured; resources reused after
        cudaStreamCreateWithFlags(&s1, cudaStreamNonBlocking);
        cudaStreamCreateWithFlags(&s2, cudaStreamNonBlocking);
        cudaEventCreateWithFlags(&ev0, cudaEventDisableTiming);
        cudaEventCreateWithFlags(&ev1, cudaEventDisableTiming);
        cudaEventCreateWithFlags(&ev2, cudaEventDisableTiming);
        cudaFuncSetAttribute(fused_gemm_kernel,
                             cudaFuncAttributeMaxDynamicSharedMemorySize, GEMM_SMEM);
    }

    // fork weight conversions
    cudaEventRecord(ev0, 0);
    cudaStreamWaitEvent(s1, ev0, 0);
    cudaStreamWaitEvent(s2, ev0, 0);
    conv_gateup_kernel<<<dim3(F / 32, H / 64, E), 256, 0, s1>>>(wg, wu);
    cudaEventRecord(ev1, s1);
    conv_down_kernel<<<dim3(F / 64, H / 32, E), 256, 0, s2>>>(wd);
    cudaEventRecord(ev2, s2);

    // router chain on the main stream
    ln_router_kernel<<<T, 256>>>(x, rw, gamma, beta);
    assign_kernel<<<E, 1024>>>();
    gather_convert_kernel<<<E * CAP, 128>>>();

    // single fused launch (needs both converted weight buffers)
    cudaStreamWaitEvent(0, ev1, 0);
    cudaStreamWaitEvent(0, ev2, 0);
    fused_gemm_kernel<<<N_ALL, 256, GEMM_SMEM>>>(x, out);
}

// round 16
// speedup vs baseline: 1.0150x; 1.0150x over previous
#include <cuda_runtime.h>
#include <cuda_bf16.h>
#include <cuda_fp16.h>
#include <cstdint>

// ---------------------------------------------------------------------------
// Problem constants
// ---------------------------------------------------------------------------
constexpr int T   = 4096;
constexpr int H   = 1024;
constexpr int F   = 2048;
constexpr int E   = 8;
constexpr int CAP = 640;

constexpr int KA1 = H;       // 1024  GEMM1 K
constexpr int KA2 = F;       // 2048  GEMM2 K
constexpr int NB1 = 2 * F;   // 4096  interleaved gate/up rows
constexpr int NB2 = H;       // 1024

constexpr int MT    = CAP / 128;                 // 5 m-tiles
constexpr int N_G1  = E * MT * (NB1 / 128);      // 1280 GEMM1 items
constexpr int N_G2  = E * MT * (NB2 / 128) * 2;  // 640  GEMM2 items (split-K 2)
constexpr int N_ALL = N_G1 + N_G2;               // 1920

// ---------------------------------------------------------------------------
// Scratch
// ---------------------------------------------------------------------------
__device__ float d_tokens_ln[(size_t)T * H];
__device__ int   d_sel[E * CAP];
__device__ int   d_valid[E * CAP];
__device__ int   d_idx[T * 2];
__device__ float d_wts[T * 2];
__device__ int   d_ready[E * MT];                 // GEMM1 completion counters
__device__ __align__(16) __half d_xin_fp[(size_t)E * CAP * KA1];
__device__ __align__(16) __half d_wgu_fp[(size_t)E * NB1 * KA1];
__device__ __align__(16) __half d_wd_fp [(size_t)E * NB2 * KA2];
__device__ __align__(16) __half d_act_fp[(size_t)E * CAP * KA2];
__device__ __align__(16) __half d_eout_fp[(size_t)2 * E * CAP * H];  // fp16 split-K partials

// ---------------------------------------------------------------------------
// PTX helpers
// ---------------------------------------------------------------------------
__device__ __forceinline__ uint32_t smem_u32(const void* p) {
    uint32_t a;
    asm("{ .reg .u64 t; cvta.to.shared.u64 t, %1; cvt.u32.u64 %0, t; }" : "=r"(a) : "l"(p));
    return a;
}
#define CP_ASYNC16(dst, src) \
    asm volatile("cp.async.cg.shared.global [%0], [%1], 16;" :: "r"(dst), "l"(src))
#define CP_COMMIT() asm volatile("cp.async.commit_group;" ::: "memory")
#define CP_WAIT2()  asm volatile("cp.async.wait_group 2;" ::: "memory")

__device__ __forceinline__ void ldmx4(uint32_t& r0, uint32_t& r1, uint32_t& r2,
                                      uint32_t& r3, uint32_t a) {
    asm volatile("ldmatrix.sync.aligned.m8n8.x4.shared.b16 {%0,%1,%2,%3}, [%4];"
                 : "=r"(r0), "=r"(r1), "=r"(r2), "=r"(r3) : "r"(a));
}
__device__ __forceinline__ void mma_f16(float* c, uint32_t a0, uint32_t a1,
                                        uint32_t a2, uint32_t a3,
                                        uint32_t b0, uint32_t b1) {
    asm volatile(
        "mma.sync.aligned.m16n8k16.row.col.f32.f16.f16.f32 "
        "{%0,%1,%2,%3}, {%4,%5,%6,%7}, {%8,%9}, {%0,%1,%2,%3};"
        : "+f"(c[0]), "+f"(c[1]), "+f"(c[2]), "+f"(c[3])
        : "r"(a0), "r"(a1), "r"(a2), "r"(a3), "r"(b0), "r"(b1));
}
__device__ __forceinline__ void spin_until(const int* p, int target) {
    int v;
    do {
        asm volatile("ld.acquire.gpu.global.b32 %0, [%1];"
                     : "=r"(v) : "l"(p) : "memory");
        if (v < target) __nanosleep(64);
    } while (v < target);
}

// ---------------------------------------------------------------------------
// Kernel A: LayerNorm + router + top-2 (one block / token), shuffle reductions
// ---------------------------------------------------------------------------
__global__ void __launch_bounds__(256) ln_router_kernel(
    const float* __restrict__ x, const float* __restrict__ rw,
    const float* __restrict__ gamma, const float* __restrict__ beta)
{
    int t   = blockIdx.x;
    int tid = threadIdx.x;
    int warp = tid >> 5, lane = tid & 31;
    const float4 v = ((const float4*)(x + (size_t)t * H))[tid];

    __shared__ float wsum[8];
    __shared__ float bcast;

    float s = v.x + v.y + v.z + v.w;
    #pragma unroll
    for (int o = 16; o > 0; o >>= 1) s += __shfl_down_sync(0xffffffffu, s, o);
    if (lane == 0) wsum[warp] = s;
    __syncthreads();
    if (warp == 0) {
        float sv = (lane < 8) ? wsum[lane] : 0.0f;
        #pragma unroll
        for (int o = 4; o > 0; o >>= 1) sv += __shfl_down_sync(0xffffffffu, sv, o);
        if (lane == 0) bcast = sv;
    }
    __syncthreads();
    float mu = bcast * (1.0f / H);
    __syncthreads();

    float dx0 = v.x - mu, dx1 = v.y - mu, dx2 = v.z - mu, dx3 = v.w - mu;
    s = dx0 * dx0 + dx1 * dx1 + dx2 * dx2 + dx3 * dx3;
    #pragma unroll
    for (int o = 16; o > 0; o >>= 1) s += __shfl_down_sync(0xffffffffu, s, o);
    if (lane == 0) wsum[warp] = s;
    __syncthreads();
    if (warp == 0) {
        float sv = (lane < 8) ? wsum[lane] : 0.0f;
        #pragma unroll
        for (int o = 4; o > 0; o >>= 1) sv += __shfl_down_sync(0xffffffffu, sv, o);
        if (lane == 0) bcast = sv;
    }
    __syncthreads();
    float rstd = rsqrtf(bcast * (1.0f / H) + 1e-5f);

    float4 g4 = ((const float4*)gamma)[tid];
    float4 b4 = ((const float4*)beta)[tid];
    float tl[4];
    tl[0] = dx0 * rstd * g4.x + b4.x;
    tl[1] = dx1 * rstd * g4.y + b4.y;
    tl[2] = dx2 * rstd * g4.z + b4.z;
    tl[3] = dx3 * rstd * g4.w + b4.w;
    ((float4*)(d_tokens_ln + (size_t)t * H))[tid] = make_float4(tl[0], tl[1], tl[2], tl[3]);

    int h0 = tid * 4;
    float acc[E];
    #pragma unroll
    for (int e = 0; e < E; e++) acc[e] = 0.0f;
    #pragma unroll
    for (int j = 0; j < 4; j++) {
        const float* rwr = rw + (size_t)(h0 + j) * E;
        #pragma unroll
        for (int e = 0; e < E; e++) acc[e] += tl[j] * rwr[e];
    }
    #pragma unroll
    for (int off = 16; off > 0; off >>= 1)
        #pragma unroll
        for (int e = 0; e < E; e++)
            acc[e] += __shfl_down_sync(0xffffffffu, acc[e], off);

    __shared__ float wlog[8][E];
    if (lane == 0)
        #pragma unroll
        for (int e = 0; e < E; e++) wlog[warp][e] = acc[e];
    __syncthreads();

    if (tid == 0) {
        float lg[E];
        #pragma unroll
        for (int e = 0; e < E; e++) {
            float sv = 0.0f;
            #pragma unroll
            for (int w = 0; w < 8; w++) sv += wlog[w][e];
            lg[e] = sv;
        }
        float mx = lg[0];
        #pragma unroll
        for (int e = 1; e < E; e++) mx = fmaxf(mx, lg[e]);
        float p[E];
        #pragma unroll
        for (int e = 0; e < E; e++) p[e] = expf(lg[e] - mx);
        int i0 = 0; float b0 = p[0];
        #pragma unroll
        for (int e = 1; e < E; e++) if (p[e] > b0) { b0 = p[e]; i0 = e; }
        int i1 = -1; float b1 = -1.0f;
        #pragma unroll
        for (int e = 0; e < E; e++) if (e != i0 && p[e] > b1) { b1 = p[e]; i1 = e; }
        float inv = 1.0f / (b0 + b1);
        d_idx[2 * t] = i0; d_idx[2 * t + 1] = i1;
        d_wts[2 * t] = b0 * inv; d_wts[2 * t + 1] = b1 * inv;
    }
}

// ---------------------------------------------------------------------------
// Kernel B: capacity assignment — single-pass block scan, one block / expert.
// Each thread owns 4 consecutive tokens (stable order preserved).
// ---------------------------------------------------------------------------
__global__ void __launch_bounds__(1024) assign_kernel()
{
    int e = blockIdx.x, tid = threadIdx.x;
    int lane = tid & 31, warp = tid >> 5;
    __shared__ int warpSum[32];
    __shared__ int s_total;

    int t0 = tid * 4;
    int m[4]; int cnt = 0;
    #pragma unroll
    for (int j = 0; j < 4; j++) {
        int t = t0 + j;
        m[j] = (d_idx[2 * t] == e) | (d_idx[2 * t + 1] == e);
        cnt += m[j];
    }
    // inclusive warp scan of per-thread counts
    int inc = cnt;
    #pragma unroll
    for (int o = 1; o < 32; o <<= 1) {
        int v = __shfl_up_sync(0xffffffffu, inc, o);
        if (lane >= o) inc += v;
    }
    if (lane == 31) warpSum[warp] = inc;
    __syncthreads();
    if (warp == 0) {
        int v = warpSum[lane];
        int iv = v;
        #pragma unroll
        for (int o = 1; o < 32; o <<= 1) {
            int u = __shfl_up_sync(0xffffffffu, iv, o);
            if (lane >= o) iv += u;
        }
        warpSum[lane] = iv - v;            // exclusive warp offset
        if (lane == 31) s_total = iv;      // total selected
    }
    __syncthreads();
    int total  = s_total;
    int selPre = warpSum[warp] + (inc - cnt);   // exclusive prefix for this thread
    #pragma unroll
    for (int j = 0; j < 4; j++) {
        int t = t0 + j;
        int pos = m[j] ? selPre : (total + t - selPre);
        if (pos < CAP) { d_sel[e * CAP + pos] = t; d_valid[e * CAP + pos] = m[j]; }
        selPre += m[j];
    }
}

// ---------------------------------------------------------------------------
// Kernel C: gather + fp16 convert; block 0 also resets the ready counters
// ---------------------------------------------------------------------------
__global__ void __launch_bounds__(128) gather_convert_kernel()
{
    int ec = blockIdx.x, tid = threadIdx.x;
    if (ec == 0 && tid < E * MT) d_ready[tid] = 0;
    int v = d_valid[ec], s = d_sel[ec];
    float4 a = make_float4(0.f,0.f,0.f,0.f), b = a;
    if (v) {
        const float4* src = (const float4*)(d_tokens_ln + (size_t)s * H);
        a = src[tid * 2]; b = src[tid * 2 + 1];
    }
    float vv[8] = {a.x, a.y, a.z, a.w, b.x, b.y, b.z, b.w};
    alignas(16) __half o[8];
    #pragma unroll
    for (int j = 0; j < 8; j++) o[j] = __float2half(vv[j]);
    ((uint4*)(d_xin_fp + (size_t)ec * KA1 + tid * 8))[0] = *(const uint4*)o;
}

// ---------------------------------------------------------------------------
// Kernel D: gate/up transpose [E][H][F] -> [E][2F][H] fp16 (rows 2f+s)
// ---------------------------------------------------------------------------
__global__ void __launch_bounds__(256) conv_gateup_kernel(
    const float* __restrict__ wg, const float* __restrict__ wu)
{
    int f0 = blockIdx.x * 32, h0 = blockIdx.y * 64, e = blockIdx.z;
    __shared__ float sg[32][65], su[32][65];
    int t = threadIdx.x, fi = t & 31, hr = t >> 5;
    #pragma unroll
    for (int it = 0; it < 8; it++) {
        int hl = hr + it * 8;
        size_t base = ((size_t)e * H + h0 + hl) * F + f0 + fi;
        sg[fi][hl] = wg[base];
        su[fi][hl] = wu[base];
    }
    __syncthreads();
    #pragma unroll
    for (int it = 0; it < 2; it++) {
        int u = t + it * 256;
        int r = u >> 3, unit = u & 7;
        int fl = r >> 1, sfl = r & 1;
        const float (*sm)[65] = sfl ? su : sg;
        alignas(16) __half o[8];
        #pragma unroll
        for (int j = 0; j < 8; j++) o[j] = __float2half(sm[fl][unit * 8 + j]);
        ((uint4*)(d_wgu_fp + ((size_t)e * NB1 + 2 * f0 + r) * KA1
                  + h0 + unit * 8))[0] = *(const uint4*)o;
    }
}

// ---------------------------------------------------------------------------
// Kernel E: down transpose [E][F][H] -> [E][H][F] fp16
// ---------------------------------------------------------------------------
__global__ void __launch_bounds__(256) conv_down_kernel(const float* __restrict__ wd)
{
    int f0 = blockIdx.x * 64, h0 = blockIdx.y * 32, e = blockIdx.z;
    __shared__ float sd[32][65];
    int t = threadIdx.x, hl = t & 31, fr = t >> 5;
    #pragma unroll
    for (int it = 0; it < 8; it++) {
        int fl = fr + it * 8;
        sd[hl][fl] = wd[((size_t)e * F + f0 + fl) * H + h0 + hl];
    }
    __syncthreads();
    {
        int r = t >> 3, unit = t & 7;
        alignas(16) __half o[8];
        #pragma unroll
        for (int j = 0; j < 8; j++) o[j] = __float2half(sd[r][unit * 8 + j]);
        ((uint4*)(d_wd_fp + ((size_t)e * NB2 + h0 + r) * KA2
                  + f0 + unit * 8))[0] = *(const uint4*)o;
    }
}

// ---------------------------------------------------------------------------
// FUSED GEMM: one launch, 1920 CTAs (GEMM1 then GEMM2 in bid order).
// GEMM2 CTAs spin on per-(e,m0) ready counters — deadlock-free by bid-order
// dispatch; GEMM2 backfills GEMM1's drain.
// ---------------------------------------------------------------------------
constexpr int STAGE_BYTES = 20480;            // A 128*80 + B 128*80
constexpr int GEMM_SMEM   = 4 * STAGE_BYTES;  // 81920

__global__ void __launch_bounds__(256, 2) fused_gemm_kernel()
{
    constexpr int NC = 32;                    // K=1024 for both item types
    extern __shared__ char smem_raw[];
    uint32_t sb = smem_u32(smem_raw);
    int tid = threadIdx.x, wid = tid >> 5, lane = tid & 31;
    int bid = blockIdx.x;
    bool g1 = bid < N_G1;

    int e, m0, n0, part = 0;
    const __half *Arow, *Brow;
    size_t ktb;
    if (g1) {
        e = bid / (MT * (NB1 / 128));
        int rem = bid % (MT * (NB1 / 128));
        m0 = (rem % MT) * 128;
        n0 = (rem / MT) * 128;
        Arow = d_xin_fp + ((size_t)e * CAP + m0) * KA1;
        Brow = d_wgu_fp + ((size_t)e * NB1 + n0) * KA1;
        ktb  = KA1 * 2;
    } else {
        int idx = bid - N_G1;
        e = idx / (MT * (NB2 / 128) * 2);
        int rem = idx % (MT * (NB2 / 128) * 2);
        part = rem & 1;
        rem >>= 1;
        m0 = (rem % MT) * 128;
        n0 = (rem / MT) * 128;
        Arow = d_act_fp + ((size_t)e * CAP + m0) * KA2 + part * (KA2 / 2);
        Brow = d_wd_fp  + ((size_t)e * NB2 + n0) * KA2 + part * (KA2 / 2);
        ktb  = KA2 * 2;
        if (tid == 0) spin_until(&d_ready[e * MT + (m0 >> 7)], 32);
        __syncthreads();
    }

    int wm0 = (wid & 3) * 32, wn0 = (wid >> 2) * 64;
    float acc[2][8][4] = {};

    auto loadst = [&](int s, int chunk) {
        uint32_t abase = sb + s * STAGE_BYTES;
        uint32_t bbase = abase + 10240;
        const char* ag = (const char*)Arow + chunk * 64;
        const char* bg = (const char*)Brow + chunk * 64;
        #pragma unroll
        for (int it = 0; it < 2; it++) {
            int u = tid + it * 256; int row = u >> 2, c = u & 3;
            CP_ASYNC16(abase + row * 80 + c * 16, ag + (size_t)row * ktb + c * 16);
        }
        #pragma unroll
        for (int it = 0; it < 2; it++) {
            int u = tid + it * 256; int row = u >> 2, c = u & 3;
            CP_ASYNC16(bbase + row * 80 + c * 16, bg + (size_t)row * ktb + c * 16);
        }
        CP_COMMIT();
    };

    #pragma unroll
    for (int s = 0; s < 3; s++) loadst(s, s);

    for (int i = 0; i < NC; i++) {
        int s = i & 3;
        CP_WAIT2();
        __syncthreads();
        if (i + 3 < NC) loadst((i + 3) & 3, i + 3);
        else            CP_COMMIT();
        uint32_t abase = sb + s * STAGE_BYTES;
        uint32_t bbase = abase + 10240;
        #pragma unroll
        for (int kk = 0; kk < 2; kk++) {
            uint32_t a[2][4];
            #pragma unroll
            for (int ms = 0; ms < 2; ms++) {
                uint32_t ad = abase + (wm0 + ms * 16 + (lane & 15)) * 80
                            + (kk * 2 + (lane >> 4)) * 16;
                ldmx4(a[ms][0], a[ms][1], a[ms][2], a[ms][3], ad);
            }
            #pragma unroll
            for (int np = 0; np < 4; np++) {
                uint32_t b0, b1, b2, b3;
                uint32_t bd = bbase + (wn0 + np * 16 + (lane & 7) + ((lane >> 4) << 3)) * 80
                            + (kk * 2 + ((lane >> 3) & 1)) * 16;
                ldmx4(b0, b1, b2, b3, bd);
                #pragma unroll
                for (int ms = 0; ms < 2; ms++) {
                    mma_f16(acc[ms][np * 2],     a[ms][0], a[ms][1], a[ms][2], a[ms][3], b0, b1);
                    mma_f16(acc[ms][np * 2 + 1], a[ms][0], a[ms][1], a[ms][2], a[ms][3], b2, b3);
                }
            }
        }
    }

    // -------- epilogue --------
    if (g1) {
        __syncthreads();
        __half* sact = (__half*)smem_raw;
        #pragma unroll
        for (int ms = 0; ms < 2; ms++) {
            #pragma unroll
            for (int np = 0; np < 8; np++) {
                int f_l = (wn0 >> 1) + np * 4 + (lane & 3);
                #pragma unroll
                for (int h = 0; h < 2; h++) {
                    int row_l = wm0 + ms * 16 + (lane >> 2) + h * 8;
                    float g  = acc[ms][np][2 * h];
                    float uu = acc[ms][np][2 * h + 1];
                    float av = (g / (1.0f + __expf(-g))) * uu;
                    sact[row_l * 64 + f_l] = __float2half(av);
                }
            }
        }
        __syncthreads();
        int row = tid >> 1, half = tid & 1;
        const uint4* src = (const uint4*)(sact + row * 64) + half * 4;
        uint4* dst = (uint4*)(d_act_fp + ((size_t)e * CAP + m0 + row) * KA2
                              + (n0 >> 1)) + half * 4;
        #pragma unroll
        for (int q = 0; q < 4; q++) dst[q] = src[q];
        __threadfence();
        __syncthreads();
        if (tid == 0) atomicAdd(&d_ready[e * MT + (m0 >> 7)], 1);
    } else {
        __half* outp = d_eout_fp + (size_t)part * E * CAP * H;
        #pragma unroll
        for (int ms = 0; ms < 2; ms++) {
            #pragma unroll
            for (int np = 0; np < 8; np++) {
                int r0 = m0 + wm0 + ms * 16 + (lane >> 2);
                int nc = n0 + wn0 + np * 8 + (lane & 3) * 2;
                #pragma unroll
                for (int h = 0; h < 2; h++) {
                    int row = r0 + h * 8;
                    __half2* p = (__half2*)(outp + ((size_t)e * CAP + row) * H + nc);
                    *p = __floats2half2_rn(acc[ms][np][2 * h], acc[ms][np][2 * h + 1]);
                }
            }
        }
    }
}

// ---------------------------------------------------------------------------
// Kernel F: combine (sums the 2 fp16 split-K partial planes), 8 h per thread
// ---------------------------------------------------------------------------
__global__ void __launch_bounds__(256) combine_kernel(
    const float* __restrict__ x, float* __restrict__ out)
{
    constexpr int PART = E * CAP * (H / 8);    // uint4 plane stride
    int i = blockIdx.x * 256 + threadIdx.x;    // uint4 index over T*H/8
    int h8 = i & (H / 8 - 1);
    int t  = i >> 7;
    int slot = min(t, CAP - 1);
    int i0 = d_idx[2 * t], i1 = d_idx[2 * t + 1];
    float w0 = d_wts[2 * t], w1 = d_wts[2 * t + 1];

    const uint4* e4 = (const uint4*)d_eout_fp;
    int idx0 = (i0 * CAP + slot) * (H / 8) + h8;
    int idx1 = (i1 * CAP + slot) * (H / 8) + h8;
    uint4 q0a = e4[idx0], q0b = e4[idx0 + PART];
    uint4 q1a = e4[idx1], q1b = e4[idx1 + PART];
    const __half2* g0a = (const __half2*)&q0a;
    const __half2* g0b = (const __half2*)&q0b;
    const __half2* g1a = (const __half2*)&q1a;
    const __half2* g1b = (const __half2*)&q1b;

    const float4* x4 = (const float4*)x;
    float4* o4 = (float4*)out;
    #pragma unroll
    for (int q = 0; q < 2; q++) {
        float4 a = x4[i * 2 + q];
        float2 p0a = __half22float2(g0a[q * 2]),     p0a1 = __half22float2(g0a[q * 2 + 1]);
        float2 p0b = __half22float2(g0b[q * 2]),     p0b1 = __half22float2(g0b[q * 2 + 1]);
        float2 p1a = __half22float2(g1a[q * 2]),     p1a1 = __half22float2(g1a[q * 2 + 1]);
        float2 p1b = __half22float2(g1b[q * 2]),     p1b1 = __half22float2(g1b[q * 2 + 1]);
        float4 o;
        o.x = a.x + w0 * (p0a.x  + p0b.x)  + w1 * (p1a.x  + p1b.x);
        o.y = a.y + w0 * (p0a.y  + p0b.y)  + w1 * (p1a.y  + p1b.y);
        o.z = a.z + w0 * (p0a1.x + p0b1.x) + w1 * (p1a1.x + p1b1.x);
        o.w = a.w + w0 * (p0a1.y + p0b1.y) + w1 * (p1a1.y + p1b1.y);
        o4[i * 2 + q] = o;
    }
}

// ---------------------------------------------------------------------------
// Launch: conv kernels on the 2 proven side streams; single fused GEMM launch
// ---------------------------------------------------------------------------
extern "C" void kernel_launch(void* const* d_in, const int* in_sizes, int n_in,
                              void* d_out, int out_size)
{
    const float* x     = (const float*)d_in[0];
    const float* rw    = (const float*)d_in[1];
    const float* wg    = (const float*)d_in[2];
    const float* wu    = (const float*)d_in[3];
    const float* wd    = (const float*)d_in[4];
    const float* gamma = (const float*)d_in[5];
    const float* beta  = (const float*)d_in[6];
    float*       out   = (float*)d_out;

    static cudaStream_t s1 = nullptr, s2 = nullptr;
    static cudaEvent_t  ev0 = nullptr, ev1 = nullptr, ev2 = nullptr;
    if (s1 == nullptr) {       // first call is uncaptured; resources reused after
        cudaStreamCreateWithFlags(&s1, cudaStreamNonBlocking);
        cudaStreamCreateWithFlags(&s2, cudaStreamNonBlocking);
        cudaEventCreateWithFlags(&ev0, cudaEventDisableTiming);
        cudaEventCreateWithFlags(&ev1, cudaEventDisableTiming);
        cudaEventCreateWithFlags(&ev2, cudaEventDisableTiming);
        cudaFuncSetAttribute(fused_gemm_kernel,
                             cudaFuncAttributeMaxDynamicSharedMemorySize, GEMM_SMEM);
    }

    // fork weight conversions
    cudaEventRecord(ev0, 0);
    cudaStreamWaitEvent(s1, ev0, 0);
    cudaStreamWaitEvent(s2, ev0, 0);
    conv_gateup_kernel<<<dim3(F / 32, H / 64, E), 256, 0, s1>>>(wg, wu);
    cudaEventRecord(ev1, s1);
    conv_down_kernel<<<dim3(F / 64, H / 32, E), 256, 0, s2>>>(wd);
    cudaEventRecord(ev2, s2);

    // router chain on the main stream
    ln_router_kernel<<<T, 256>>>(x, rw, gamma, beta);
    assign_kernel<<<E, 1024>>>();
    gather_convert_kernel<<<E * CAP, 128>>>();

    // single fused GEMM launch (needs both converted weight buffers)
    cudaStreamWaitEvent(0, ev1, 0);
    cudaStreamWaitEvent(0, ev2, 0);
    fused_gemm_kernel<<<N_ALL, 256, GEMM_SMEM>>>();

    combine_kernel<<<(T * H / 8) / 256, 256>>>(x, out);
}

// round 17
// speedup vs baseline: 1.0868x; 1.0707x over previous
#include <cuda_runtime.h>
#include <cuda_bf16.h>
#include <cuda_fp16.h>
#include <cstdint>

// ---------------------------------------------------------------------------
// Problem constants
// ---------------------------------------------------------------------------
constexpr int T   = 4096;
constexpr int H   = 1024;
constexpr int F   = 2048;
constexpr int E   = 8;
constexpr int CAP = 640;

constexpr int KA1 = H;       // 1024  GEMM1 K
constexpr int KA2 = F;       // 2048  GEMM2 K
constexpr int NB1 = 2 * F;   // 4096  interleaved gate/up rows
constexpr int NB2 = H;       // 1024

constexpr int MT    = CAP / 128;                 // 5 m-tiles
constexpr int N_G1  = E * MT * (NB1 / 128);      // 1280 GEMM1 items
constexpr int N_G2  = E * MT * (NB2 / 128) * 2;  // 640  GEMM2 items (split-K 2)
constexpr int N_ALL = N_G1 + N_G2;               // 1920

// ---------------------------------------------------------------------------
// Scratch
// ---------------------------------------------------------------------------
__device__ float d_tokens_ln[(size_t)T * H];
__device__ int   d_sel[E * CAP];
__device__ int   d_valid[E * CAP];
__device__ int   d_idx[T * 2];
__device__ float d_wts[T * 2];
__device__ int   d_ready[E * MT];                 // GEMM1 completion counters
__device__ __align__(16) __half d_xin_fp[(size_t)E * CAP * KA1];
__device__ __align__(16) __half d_wgu_fp[(size_t)E * NB1 * KA1];
__device__ __align__(16) __half d_wd_fp [(size_t)E * NB2 * KA2];
__device__ __align__(16) __half d_act_fp[(size_t)E * CAP * KA2];
__device__ __align__(16) __half d_eout_fp[(size_t)2 * E * CAP * H];  // fp16 split-K partials

// ---------------------------------------------------------------------------
// PTX helpers
// ---------------------------------------------------------------------------
__device__ __forceinline__ uint32_t smem_u32(const void* p) {
    uint32_t a;
    asm("{ .reg .u64 t; cvta.to.shared.u64 t, %1; cvt.u32.u64 %0, t; }" : "=r"(a) : "l"(p));
    return a;
}
#define CP_ASYNC16(dst, src) \
    asm volatile("cp.async.cg.shared.global [%0], [%1], 16;" :: "r"(dst), "l"(src))
#define CP_COMMIT() asm volatile("cp.async.commit_group;" ::: "memory")
#define CP_WAIT1()  asm volatile("cp.async.wait_group 1;" ::: "memory")

__device__ __forceinline__ void ldmx4(uint32_t& r0, uint32_t& r1, uint32_t& r2,
                                      uint32_t& r3, uint32_t a) {
    asm volatile("ldmatrix.sync.aligned.m8n8.x4.shared.b16 {%0,%1,%2,%3}, [%4];"
                 : "=r"(r0), "=r"(r1), "=r"(r2), "=r"(r3) : "r"(a));
}
__device__ __forceinline__ void mma_f16(float* c, uint32_t a0, uint32_t a1,
                                        uint32_t a2, uint32_t a3,
                                        uint32_t b0, uint32_t b1) {
    asm volatile(
        "mma.sync.aligned.m16n8k16.row.col.f32.f16.f16.f32 "
        "{%0,%1,%2,%3}, {%4,%5,%6,%7}, {%8,%9}, {%0,%1,%2,%3};"
        : "+f"(c[0]), "+f"(c[1]), "+f"(c[2]), "+f"(c[3])
        : "r"(a0), "r"(a1), "r"(a2), "r"(a3), "r"(b0), "r"(b1));
}
__device__ __forceinline__ void spin_until(const int* p, int target) {
    int v;
    do {
        asm volatile("ld.acquire.gpu.global.b32 %0, [%1];"
                     : "=r"(v) : "l"(p) : "memory");
        if (v < target) __nanosleep(64);
    } while (v < target);
}

// ---------------------------------------------------------------------------
// Kernel A: LayerNorm + router + top-2 (one block / token), shuffle reductions
// ---------------------------------------------------------------------------
__global__ void __launch_bounds__(256) ln_router_kernel(
    const float* __restrict__ x, const float* __restrict__ rw,
    const float* __restrict__ gamma, const float* __restrict__ beta)
{
    int t   = blockIdx.x;
    int tid = threadIdx.x;
    int warp = tid >> 5, lane = tid & 31;
    const float4 v = ((const float4*)(x + (size_t)t * H))[tid];

    __shared__ float wsum[8];
    __shared__ float bcast;

    float s = v.x + v.y + v.z + v.w;
    #pragma unroll
    for (int o = 16; o > 0; o >>= 1) s += __shfl_down_sync(0xffffffffu, s, o);
    if (lane == 0) wsum[warp] = s;
    __syncthreads();
    if (warp == 0) {
        float sv = (lane < 8) ? wsum[lane] : 0.0f;
        #pragma unroll
        for (int o = 4; o > 0; o >>= 1) sv += __shfl_down_sync(0xffffffffu, sv, o);
        if (lane == 0) bcast = sv;
    }
    __syncthreads();
    float mu = bcast * (1.0f / H);
    __syncthreads();

    float dx0 = v.x - mu, dx1 = v.y - mu, dx2 = v.z - mu, dx3 = v.w - mu;
    s = dx0 * dx0 + dx1 * dx1 + dx2 * dx2 + dx3 * dx3;
    #pragma unroll
    for (int o = 16; o > 0; o >>= 1) s += __shfl_down_sync(0xffffffffu, s, o);
    if (lane == 0) wsum[warp] = s;
    __syncthreads();
    if (warp == 0) {
        float sv = (lane < 8) ? wsum[lane] : 0.0f;
        #pragma unroll
        for (int o = 4; o > 0; o >>= 1) sv += __shfl_down_sync(0xffffffffu, sv, o);
        if (lane == 0) bcast = sv;
    }
    __syncthreads();
    float rstd = rsqrtf(bcast * (1.0f / H) + 1e-5f);

    float4 g4 = ((const float4*)gamma)[tid];
    float4 b4 = ((const float4*)beta)[tid];
    float tl[4];
    tl[0] = dx0 * rstd * g4.x + b4.x;
    tl[1] = dx1 * rstd * g4.y + b4.y;
    tl[2] = dx2 * rstd * g4.z + b4.z;
    tl[3] = dx3 * rstd * g4.w + b4.w;
    ((float4*)(d_tokens_ln + (size_t)t * H))[tid] = make_float4(tl[0], tl[1], tl[2], tl[3]);

    int h0 = tid * 4;
    float acc[E];
    #pragma unroll
    for (int e = 0; e < E; e++) acc[e] = 0.0f;
    #pragma unroll
    for (int j = 0; j < 4; j++) {
        const float* rwr = rw + (size_t)(h0 + j) * E;
        #pragma unroll
        for (int e = 0; e < E; e++) acc[e] += tl[j] * rwr[e];
    }
    #pragma unroll
    for (int off = 16; off > 0; off >>= 1)
        #pragma unroll
        for (int e = 0; e < E; e++)
            acc[e] += __shfl_down_sync(0xffffffffu, acc[e], off);

    __shared__ float wlog[8][E];
    if (lane == 0)
        #pragma unroll
        for (int e = 0; e < E; e++) wlog[warp][e] = acc[e];
    __syncthreads();

    if (tid == 0) {
        float lg[E];
        #pragma unroll
        for (int e = 0; e < E; e++) {
            float sv = 0.0f;
            #pragma unroll
            for (int w = 0; w < 8; w++) sv += wlog[w][e];
            lg[e] = sv;
        }
        float mx = lg[0];
        #pragma unroll
        for (int e = 1; e < E; e++) mx = fmaxf(mx, lg[e]);
        float p[E];
        #pragma unroll
        for (int e = 0; e < E; e++) p[e] = expf(lg[e] - mx);
        int i0 = 0; float b0 = p[0];
        #pragma unroll
        for (int e = 1; e < E; e++) if (p[e] > b0) { b0 = p[e]; i0 = e; }
        int i1 = -1; float b1 = -1.0f;
        #pragma unroll
        for (int e = 0; e < E; e++) if (e != i0 && p[e] > b1) { b1 = p[e]; i1 = e; }
        float inv = 1.0f / (b0 + b1);
        d_idx[2 * t] = i0; d_idx[2 * t + 1] = i1;
        d_wts[2 * t] = b0 * inv; d_wts[2 * t + 1] = b1 * inv;
    }
}

// ---------------------------------------------------------------------------
// Kernel B: capacity assignment — single-pass block scan, one block / expert.
// ---------------------------------------------------------------------------
__global__ void __launch_bounds__(1024) assign_kernel()
{
    int e = blockIdx.x, tid = threadIdx.x;
    int lane = tid & 31, warp = tid >> 5;
    __shared__ int warpSum[32];
    __shared__ int s_total;

    int t0 = tid * 4;
    int m[4]; int cnt = 0;
    #pragma unroll
    for (int j = 0; j < 4; j++) {
        int t = t0 + j;
        m[j] = (d_idx[2 * t] == e) | (d_idx[2 * t + 1] == e);
        cnt += m[j];
    }
    int inc = cnt;
    #pragma unroll
    for (int o = 1; o < 32; o <<= 1) {
        int v = __shfl_up_sync(0xffffffffu, inc, o);
        if (lane >= o) inc += v;
    }
    if (lane == 31) warpSum[warp] = inc;
    __syncthreads();
    if (warp == 0) {
        int v = warpSum[lane];
        int iv = v;
        #pragma unroll
        for (int o = 1; o < 32; o <<= 1) {
            int u = __shfl_up_sync(0xffffffffu, iv, o);
            if (lane >= o) iv += u;
        }
        warpSum[lane] = iv - v;
        if (lane == 31) s_total = iv;
    }
    __syncthreads();
    int total  = s_total;
    int selPre = warpSum[warp] + (inc - cnt);
    #pragma unroll
    for (int j = 0; j < 4; j++) {
        int t = t0 + j;
        int pos = m[j] ? selPre : (total + t - selPre);
        if (pos < CAP) { d_sel[e * CAP + pos] = t; d_valid[e * CAP + pos] = m[j]; }
        selPre += m[j];
    }
}

// ---------------------------------------------------------------------------
// Kernel C: gather + fp16 convert; block 0 also resets the ready counters
// ---------------------------------------------------------------------------
__global__ void __launch_bounds__(128) gather_convert_kernel()
{
    int ec = blockIdx.x, tid = threadIdx.x;
    if (ec == 0 && tid < E * MT) d_ready[tid] = 0;
    int v = d_valid[ec], s = d_sel[ec];
    float4 a = make_float4(0.f,0.f,0.f,0.f), b = a;
    if (v) {
        const float4* src = (const float4*)(d_tokens_ln + (size_t)s * H);
        a = src[tid * 2]; b = src[tid * 2 + 1];
    }
    float vv[8] = {a.x, a.y, a.z, a.w, b.x, b.y, b.z, b.w};
    alignas(16) __half o[8];
    #pragma unroll
    for (int j = 0; j < 8; j++) o[j] = __float2half(vv[j]);
    ((uint4*)(d_xin_fp + (size_t)ec * KA1 + tid * 8))[0] = *(const uint4*)o;
}

// ---------------------------------------------------------------------------
// Kernel D: gate/up transpose [E][H][F] -> [E][2F][H] fp16 (rows 2f+s)
// ---------------------------------------------------------------------------
__global__ void __launch_bounds__(256) conv_gateup_kernel(
    const float* __restrict__ wg, const float* __restrict__ wu)
{
    int f0 = blockIdx.x * 32, h0 = blockIdx.y * 64, e = blockIdx.z;
    __shared__ float sg[32][65], su[32][65];
    int t = threadIdx.x, fi = t & 31, hr = t >> 5;
    #pragma unroll
    for (int it = 0; it < 8; it++) {
        int hl = hr + it * 8;
        size_t base = ((size_t)e * H + h0 + hl) * F + f0 + fi;
        sg[fi][hl] = wg[base];
        su[fi][hl] = wu[base];
    }
    __syncthreads();
    #pragma unroll
    for (int it = 0; it < 2; it++) {
        int u = t + it * 256;
        int r = u >> 3, unit = u & 7;
        int fl = r >> 1, sfl = r & 1;
        const float (*sm)[65] = sfl ? su : sg;
        alignas(16) __half o[8];
        #pragma unroll
        for (int j = 0; j < 8; j++) o[j] = __float2half(sm[fl][unit * 8 + j]);
        ((uint4*)(d_wgu_fp + ((size_t)e * NB1 + 2 * f0 + r) * KA1
                  + h0 + unit * 8))[0] = *(const uint4*)o;
    }
}

// ---------------------------------------------------------------------------
// Kernel E: down transpose [E][F][H] -> [E][H][F] fp16
// ---------------------------------------------------------------------------
__global__ void __launch_bounds__(256) conv_down_kernel(const float* __restrict__ wd)
{
    int f0 = blockIdx.x * 64, h0 = blockIdx.y * 32, e = blockIdx.z;
    __shared__ float sd[32][65];
    int t = threadIdx.x, hl = t & 31, fr = t >> 5;
    #pragma unroll
    for (int it = 0; it < 8; it++) {
        int fl = fr + it * 8;
        sd[hl][fl] = wd[((size_t)e * F + f0 + fl) * H + h0 + hl];
    }
    __syncthreads();
    {
        int r = t >> 3, unit = t & 7;
        alignas(16) __half o[8];
        #pragma unroll
        for (int j = 0; j < 8; j++) o[j] = __float2half(sd[r][unit * 8 + j]);
        ((uint4*)(d_wd_fp + ((size_t)e * NB2 + h0 + r) * KA2
                  + f0 + unit * 8))[0] = *(const uint4*)o;
    }
}

// ---------------------------------------------------------------------------
// FUSED GEMM: one launch, 1920 CTAs (GEMM1 then GEMM2 in bid order).
// BK=64, 3 slots (110592B smem), occ 2, ONE __syncthreads per K-iter (16 iters).
// Row stride 144B (=9*16B): conflict-free ldmatrix/cp.async permutation.
// GEMM2 CTAs spin on per-(e,m0) ready counters — deadlock-free by bid order.
// ---------------------------------------------------------------------------
constexpr int ROWB        = 144;                       // bytes per smem row
constexpr int STAGE_BYTES = 2 * 128 * ROWB;            // A + B = 36864
constexpr int GEMM_SMEM   = 3 * STAGE_BYTES;           // 110592

__global__ void __launch_bounds__(256, 2) fused_gemm_kernel()
{
    constexpr int NC = 16;                    // K=1024 / BK=64 for both types
    extern __shared__ char smem_raw[];
    uint32_t sb = smem_u32(smem_raw);
    int tid = threadIdx.x, wid = tid >> 5, lane = tid & 31;
    int bid = blockIdx.x;
    bool g1 = bid < N_G1;

    int e, m0, n0, part = 0;
    const __half *Arow, *Brow;
    size_t ktb;
    if (g1) {
        e = bid / (MT * (NB1 / 128));
        int rem = bid % (MT * (NB1 / 128));
        m0 = (rem % MT) * 128;
        n0 = (rem / MT) * 128;
        Arow = d_xin_fp + ((size_t)e * CAP + m0) * KA1;
        Brow = d_wgu_fp + ((size_t)e * NB1 + n0) * KA1;
        ktb  = KA1 * 2;
    } else {
        int idx = bid - N_G1;
        e = idx / (MT * (NB2 / 128) * 2);
        int rem = idx % (MT * (NB2 / 128) * 2);
        part = rem & 1;
        rem >>= 1;
        m0 = (rem % MT) * 128;
        n0 = (rem / MT) * 128;
        Arow = d_act_fp + ((size_t)e * CAP + m0) * KA2 + part * (KA2 / 2);
        Brow = d_wd_fp  + ((size_t)e * NB2 + n0) * KA2 + part * (KA2 / 2);
        ktb  = KA2 * 2;
        if (tid == 0) spin_until(&d_ready[e * MT + (m0 >> 7)], 32);
        __syncthreads();
    }

    int wm0 = (wid & 3) * 32, wn0 = (wid >> 2) * 64;
    float acc[2][8][4] = {};

    auto loadst = [&](int s, int chunk) {
        uint32_t abase = sb + s * STAGE_BYTES;
        uint32_t bbase = abase + 128 * ROWB;
        const char* ag = (const char*)Arow + chunk * 128;   // 64 halves
        const char* bg = (const char*)Brow + chunk * 128;
        #pragma unroll
        for (int it = 0; it < 4; it++) {                    // A: 1024 16B units
            int u = tid + it * 256; int row = u >> 3, c = u & 7;
            CP_ASYNC16(abase + row * ROWB + c * 16, ag + (size_t)row * ktb + c * 16);
        }
        #pragma unroll
        for (int it = 0; it < 4; it++) {                    // B: 1024 16B units
            int u = tid + it * 256; int row = u >> 3, c = u & 7;
            CP_ASYNC16(bbase + row * ROWB + c * 16, bg + (size_t)row * ktb + c * 16);
        }
        CP_COMMIT();
    };

    // prologue: 2 chunks in flight (3 smem slots)
    loadst(0, 0);
    loadst(1, 1);

    for (int i = 0; i < NC; i++) {
        int s = i % 3;
        CP_WAIT1();              // chunk i complete (chunk i+1 may be pending)
        __syncthreads();         // all warps done reading slot (i+2)%3 at iter i-1
        if (i + 2 < NC) loadst((i + 2) % 3, i + 2);
        else            CP_COMMIT();                 // empty group keeps count
        uint32_t abase = sb + s * STAGE_BYTES;
        uint32_t bbase = abase + 128 * ROWB;
        #pragma unroll
        for (int kk = 0; kk < 4; kk++) {
            uint32_t a[2][4];
            #pragma unroll
            for (int ms = 0; ms < 2; ms++) {
                uint32_t ad = abase + (wm0 + ms * 16 + (lane & 15)) * ROWB
                            + (kk * 2 + (lane >> 4)) * 16;
                ldmx4(a[ms][0], a[ms][1], a[ms][2], a[ms][3], ad);
            }
            #pragma unroll
            for (int np = 0; np < 4; np++) {
                uint32_t b0, b1, b2, b3;
                uint32_t bd = bbase + (wn0 + np * 16 + (lane & 7) + ((lane >> 4) << 3)) * ROWB
                            + (kk * 2 + ((lane >> 3) & 1)) * 16;
                ldmx4(b0, b1, b2, b3, bd);
                #pragma unroll
                for (int ms = 0; ms < 2; ms++) {
                    mma_f16(acc[ms][np * 2],     a[ms][0], a[ms][1], a[ms][2], a[ms][3], b0, b1);
                    mma_f16(acc[ms][np * 2 + 1], a[ms][0], a[ms][1], a[ms][2], a[ms][3], b2, b3);
                }
            }
        }
    }

    // -------- epilogue --------
    if (g1) {
        __syncthreads();
        __half* sact = (__half*)smem_raw;
        #pragma unroll
        for (int ms = 0; ms < 2; ms++) {
            #pragma unroll
            for (int np = 0; np < 8; np++) {
                int f_l = (wn0 >> 1) + np * 4 + (lane & 3);
                #pragma unroll
                for (int h = 0; h < 2; h++) {
                    int row_l = wm0 + ms * 16 + (lane >> 2) + h * 8;
                    float g  = acc[ms][np][2 * h];
                    float uu = acc[ms][np][2 * h + 1];
                    float av = (g / (1.0f + __expf(-g))) * uu;
                    sact[row_l * 64 + f_l] = __float2half(av);
                }
            }
        }
        __syncthreads();
        int row = tid >> 1, half = tid & 1;
        const uint4* src = (const uint4*)(sact + row * 64) + half * 4;
        uint4* dst = (uint4*)(d_act_fp + ((size_t)e * CAP + m0 + row) * KA2
                              + (n0 >> 1)) + half * 4;
        #pragma unroll
        for (int q = 0; q < 4; q++) dst[q] = src[q];
        __threadfence();
        __syncthreads();
        if (tid == 0) atomicAdd(&d_ready[e * MT + (m0 >> 7)], 1);
    } else {
        __half* outp = d_eout_fp + (size_t)part * E * CAP * H;
        #pragma unroll
        for (int ms = 0; ms < 2; ms++) {
            #pragma unroll
            for (int np = 0; np < 8; np++) {
                int r0 = m0 + wm0 + ms * 16 + (lane >> 2);
                int nc = n0 + wn0 + np * 8 + (lane & 3) * 2;
                #pragma unroll
                for (int h = 0; h < 2; h++) {
                    int row = r0 + h * 8;
                    __half2* p = (__half2*)(outp + ((size_t)e * CAP + row) * H + nc);
                    *p = __floats2half2_rn(acc[ms][np][2 * h], acc[ms][np][2 * h + 1]);
                }
            }
        }
    }
}

// ---------------------------------------------------------------------------
// Kernel F: combine (sums the 2 fp16 split-K partial planes), 8 h per thread
// ---------------------------------------------------------------------------
__global__ void __launch_bounds__(256) combine_kernel(
    const float* __restrict__ x, float* __restrict__ out)
{
    constexpr int PART = E * CAP * (H / 8);    // uint4 plane stride
    int i = blockIdx.x * 256 + threadIdx.x;    // uint4 index over T*H/8
    int h8 = i & (H / 8 - 1);
    int t  = i >> 7;
    int slot = min(t, CAP - 1);
    int i0 = d_idx[2 * t], i1 = d_idx[2 * t + 1];
    float w0 = d_wts[2 * t], w1 = d_wts[2 * t + 1];

    const uint4* e4 = (const uint4*)d_eout_fp;
    int idx0 = (i0 * CAP + slot) * (H / 8) + h8;
    int idx1 = (i1 * CAP + slot) * (H / 8) + h8;
    uint4 q0a = e4[idx0], q0b = e4[idx0 + PART];
    uint4 q1a = e4[idx1], q1b = e4[idx1 + PART];
    const __half2* g0a = (const __half2*)&q0a;
    const __half2* g0b = (const __half2*)&q0b;
    const __half2* g1a = (const __half2*)&q1a;
    const __half2* g1b = (const __half2*)&q1b;

    const float4* x4 = (const float4*)x;
    float4* o4 = (float4*)out;
    #pragma unroll
    for (int q = 0; q < 2; q++) {
        float4 a = x4[i * 2 + q];
        float2 p0a = __half22float2(g0a[q * 2]),     p0a1 = __half22float2(g0a[q * 2 + 1]);
        float2 p0b = __half22float2(g0b[q * 2]),     p0b1 = __half22float2(g0b[q * 2 + 1]);
        float2 p1a = __half22float2(g1a[q * 2]),     p1a1 = __half22float2(g1a[q * 2 + 1]);
        float2 p1b = __half22float2(g1b[q * 2]),     p1b1 = __half22float2(g1b[q * 2 + 1]);
        float4 o;
        o.x = a.x + w0 * (p0a.x  + p0b.x)  + w1 * (p1a.x  + p1b.x);
        o.y = a.y + w0 * (p0a.y  + p0b.y)  + w1 * (p1a.y  + p1b.y);
        o.z = a.z + w0 * (p0a1.x + p0b1.x) + w1 * (p1a1.x + p1b1.x);
        o.w = a.w + w0 * (p0a1.y + p0b1.y) + w1 * (p1a1.y + p1b1.y);
        o4[i * 2 + q] = o;
    }
}

// ---------------------------------------------------------------------------
// Launch: conv kernels on the 2 proven side streams; single fused GEMM launch
// ---------------------------------------------------------------------------
extern "C" void kernel_launch(void* const* d_in, const int* in_sizes, int n_in,
                              void* d_out, int out_size)
{
    const float* x     = (const float*)d_in[0];
    const float* rw    = (const float*)d_in[1];
    const float* wg    = (const float*)d_in[2];
    const float* wu    = (const float*)d_in[3];
    const float* wd    = (const float*)d_in[4];
    const float* gamma = (const float*)d_in[5];
    const float* beta  = (const float*)d_in[6];
    float*       out   = (float*)d_out;

    static cudaStream_t s1 = nullptr, s2 = nullptr;
    static cudaEvent_t  ev0 = nullptr, ev1 = nullptr, ev2 = nullptr;
    if (s1 == nullptr) {       // first call is uncaptured; resources reused after
        cudaStreamCreateWithFlags(&s1, cudaStreamNonBlocking);
        cudaStreamCreateWithFlags(&s2, cudaStreamNonBlocking);
        cudaEventCreateWithFlags(&ev0, cudaEventDisableTiming);
        cudaEventCreateWithFlags(&ev1, cudaEventDisableTiming);
        cudaEventCreateWithFlags(&ev2, cudaEventDisableTiming);
        cudaFuncSetAttribute(fused_gemm_kernel,
                             cudaFuncAttributeMaxDynamicSharedMemorySize, GEMM_SMEM);
    }

    // fork weight conversions
    cudaEventRecord(ev0, 0);
    cudaStreamWaitEvent(s1, ev0, 0);
    cudaStreamWaitEvent(s2, ev0, 0);
    conv_gateup_kernel<<<dim3(F / 32, H / 64, E), 256, 0, s1>>>(wg, wu);
    cudaEventRecord(ev1, s1);
    conv_down_kernel<<<dim3(F / 64, H / 32, E), 256, 0, s2>>>(wd);
    cudaEventRecord(ev2, s2);

    // router chain on the main stream
    ln_router_kernel<<<T, 256>>>(x, rw, gamma, beta);
    assign_kernel<<<E, 1024>>>();
    gather_convert_kernel<<<E * CAP, 128>>>();

    // single fused GEMM launch (needs both converted weight buffers)
    cudaStreamWaitEvent(0, ev1, 0);
    cudaStreamWaitEvent(0, ev2, 0);
    fused_gemm_kernel<<<N_ALL, 256, GEMM_SMEM>>>();

    combine_kernel<<<(T * H / 8) / 256, 256>>>(x, out);
}